// round 1
// baseline (speedup 1.0000x reference)
#include <cuda_runtime.h>
#include <math_constants.h>

#define D        256
#define NSLOTS   100000
#define NBLK     296          // 2 CTAs per SM (148 SMs)
#define THREADS  256
#define WARPS    (THREADS / 32)
#define NW       (NBLK * WARPS)

// ---- device scratch (no allocations allowed) ----
__device__ __align__(16) float g_u[D];
__device__ __align__(16) float g_v[D];
__device__ float g_pmax[NBLK];
__device__ float g_psum[NBLK];
__device__ __align__(16) float g_pacc[NBLK * D];

// u0 = B @ q ; v0 = A^T u0
__global__ void init_kernel(const float* __restrict__ q,
                            const float* __restrict__ A,
                            const float* __restrict__ B) {
    __shared__ float qs[D];
    __shared__ float us[D];
    int t = threadIdx.x;
    qs[t] = q[t];
    __syncthreads();
    float u = 0.f;
#pragma unroll 8
    for (int k = 0; k < D; k++) u = fmaf(B[t * D + k], qs[k], u);
    g_u[t] = u;
    us[t] = u;
    __syncthreads();
    float v = 0.f;
#pragma unroll 8
    for (int j = 0; j < D; j++) v = fmaf(A[j * D + t], us[j], v);
    g_v[t] = v;
}

// One fused pass over memory: s_i = mem_i . v, online softmax,
// running weighted accumulation of mem_i. Per-CTA partials out.
__global__ void __launch_bounds__(THREADS, 2)
flash_kernel(const float* __restrict__ memory) {
    const int lane = threadIdx.x & 31;
    const int warp = threadIdx.x >> 5;
    const int gw   = blockIdx.x * WARPS + warp;

    // thread owns dims [lane*8, lane*8+8)
    float4 v0 = *reinterpret_cast<const float4*>(g_v + lane * 8);
    float4 v1 = *reinterpret_cast<const float4*>(g_v + lane * 8 + 4);

    float mx = -CUDART_INF_F;
    float sm = 0.f;
    float acc[8];
#pragma unroll
    for (int i = 0; i < 8; i++) acc[i] = 0.f;

    const float4* base = reinterpret_cast<const float4*>(memory);

#pragma unroll 2
    for (int slot = gw; slot < NSLOTS; slot += NW) {
        const float4* row = base + (size_t)slot * (D / 4) + lane * 2;
        float4 a = row[0];
        float4 b = row[1];

        float d = a.x * v0.x;
        d = fmaf(a.y, v0.y, d);
        d = fmaf(a.z, v0.z, d);
        d = fmaf(a.w, v0.w, d);
        d = fmaf(b.x, v1.x, d);
        d = fmaf(b.y, v1.y, d);
        d = fmaf(b.z, v1.z, d);
        d = fmaf(b.w, v1.w, d);
        d += __shfl_xor_sync(0xffffffffu, d, 16);
        d += __shfl_xor_sync(0xffffffffu, d, 8);
        d += __shfl_xor_sync(0xffffffffu, d, 4);
        d += __shfl_xor_sync(0xffffffffu, d, 2);
        d += __shfl_xor_sync(0xffffffffu, d, 1);
        // d is warp-uniform -> branch is warp-uniform
        if (d > mx) {
            float scale = __expf(mx - d);   // 0 on first iter (mx=-inf)
            mx = d;
            sm *= scale;
#pragma unroll
            for (int i = 0; i < 8; i++) acc[i] *= scale;
        }
        float w = __expf(d - mx);
        sm += w;
        acc[0] = fmaf(w, a.x, acc[0]);
        acc[1] = fmaf(w, a.y, acc[1]);
        acc[2] = fmaf(w, a.z, acc[2]);
        acc[3] = fmaf(w, a.w, acc[3]);
        acc[4] = fmaf(w, b.x, acc[4]);
        acc[5] = fmaf(w, b.y, acc[5]);
        acc[6] = fmaf(w, b.z, acc[6]);
        acc[7] = fmaf(w, b.w, acc[7]);
    }

    // combine the 8 warps of this CTA
    __shared__ float s_mx[WARPS];
    __shared__ float s_sm[WARPS];
    __shared__ float s_acc[WARPS][D];
    if (lane == 0) { s_mx[warp] = mx; s_sm[warp] = sm; }
#pragma unroll
    for (int i = 0; i < 8; i++) s_acc[warp][lane * 8 + i] = acc[i];
    __syncthreads();

    const int t = threadIdx.x;
    float M = s_mx[0];
#pragma unroll
    for (int w = 1; w < WARPS; w++) M = fmaxf(M, s_mx[w]);
    float tot = 0.f;
#pragma unroll
    for (int w = 0; w < WARPS; w++) tot = fmaf(s_acc[w][t], __expf(s_mx[w] - M), tot);
    g_pacc[blockIdx.x * D + t] = tot;
    if (t == 0) {
        float S = 0.f;
#pragma unroll
        for (int w = 0; w < WARPS; w++) S = fmaf(s_sm[w], __expf(s_mx[w] - M), S);
        g_psum[blockIdx.x] = S;
        g_pmax[blockIdx.x] = M;
    }
}

// Reduce CTA partials -> m = memory^T p ; o = C @ m ; u += o ; v = A^T u
__global__ void reduce_kernel(const float* __restrict__ A,
                              const float* __restrict__ C,
                              float* __restrict__ out, int last) {
    __shared__ float m_sh[D];
    __shared__ float u_sh[D];
    const int t = threadIdx.x;

    float M = -CUDART_INF_F;
    for (int c = 0; c < NBLK; c++) M = fmaxf(M, g_pmax[c]);
    float S = 0.f;
    for (int c = 0; c < NBLK; c++) S = fmaf(g_psum[c], __expf(g_pmax[c] - M), S);
    float acc = 0.f;
    for (int c = 0; c < NBLK; c++)
        acc = fmaf(g_pacc[c * D + t], __expf(g_pmax[c] - M), acc);
    m_sh[t] = acc / S;
    __syncthreads();

    float o = 0.f;
#pragma unroll 8
    for (int k = 0; k < D; k++) o = fmaf(C[t * D + k], m_sh[k], o);

    float u = g_u[t] + o;
    g_u[t] = u;
    u_sh[t] = u;
    if (last) out[t] = u;
    __syncthreads();

    float v = 0.f;
#pragma unroll 8
    for (int j = 0; j < D; j++) v = fmaf(A[j * D + t], u_sh[j], v);
    g_v[t] = v;
}

extern "C" void kernel_launch(void* const* d_in, const int* in_sizes, int n_in,
                              void* d_out, int out_size) {
    const float* memory = (const float*)d_in[0];
    const float* query  = (const float*)d_in[1];
    const float* A      = (const float*)d_in[2];
    const float* B      = (const float*)d_in[3];
    const float* C      = (const float*)d_in[4];
    float* out = (float*)d_out;

    init_kernel<<<1, THREADS>>>(query, A, B);
    for (int h = 0; h < 3; h++) {
        flash_kernel<<<NBLK, THREADS>>>(memory);
        reduce_kernel<<<1, THREADS>>>(A, C, out, h == 2);
    }
}

// round 2
// speedup vs baseline: 2.8557x; 2.8557x over previous
#include <cuda_runtime.h>
#include <math_constants.h>

#define D        256
#define NSLOTS   100000
#define NBLK     592          // 4 CTAs per SM (148 SMs)
#define THREADS  256
#define WARPS    (THREADS / 32)
#define NW       (NBLK * WARPS)
#define RTHREADS 1024

// ---- device scratch (no allocations allowed) ----
__device__ __align__(16) float g_u[D];
__device__ __align__(16) float g_v[D];
__device__ float g_pmax[NBLK];
__device__ float g_psum[NBLK];
__device__ __align__(16) float g_pacc[NBLK * D];

__device__ __forceinline__ float warp_sum(float d) {
#pragma unroll
    for (int m = 16; m >= 1; m >>= 1) d += __shfl_xor_sync(0xffffffffu, d, m);
    return d;
}

// u0 = B @ q ; v0 = A^T u0   (1024 threads, coalesced)
__global__ void init_kernel(const float* __restrict__ q,
                            const float* __restrict__ A,
                            const float* __restrict__ B) {
    __shared__ float qs[D];
    __shared__ float us[D];
    __shared__ float gv[4][D];
    const int t = threadIdx.x;
    const int warp = t >> 5, lane = t & 31;
    if (t < D) qs[t] = q[t];
    __syncthreads();

    // u[row] = B[row,:] . q  — warp per row, coalesced float4 row read
    for (int row = warp; row < D; row += RTHREADS / 32) {
        const float4* r = reinterpret_cast<const float4*>(B + row * D);
        float4 c0 = r[lane * 2], c1 = r[lane * 2 + 1];
        float d = c0.x * qs[lane * 8 + 0] + c0.y * qs[lane * 8 + 1]
                + c0.z * qs[lane * 8 + 2] + c0.w * qs[lane * 8 + 3]
                + c1.x * qs[lane * 8 + 4] + c1.y * qs[lane * 8 + 5]
                + c1.z * qs[lane * 8 + 6] + c1.w * qs[lane * 8 + 7];
        d = warp_sum(d);
        if (lane == 0) { us[row] = d; g_u[row] = d; }
    }
    __syncthreads();

    // v[t] = sum_j A[j,t] * u[j] — coalesced over t, 4 j-groups
    const int grp = t >> 8, dd = t & 255;
    float v = 0.f;
#pragma unroll 8
    for (int j = grp * 64; j < grp * 64 + 64; j++)
        v = fmaf(A[j * D + dd], us[j], v);
    gv[grp][dd] = v;
    __syncthreads();
    if (t < D) g_v[t] = gv[0][t] + gv[1][t] + gv[2][t] + gv[3][t];
}

// One fused pass over memory: s_i = mem_i . v, online softmax,
// running weighted accumulation of mem_i. Per-CTA partials out.
__global__ void __launch_bounds__(THREADS, 4)
flash_kernel(const float* __restrict__ memory) {
    const int lane = threadIdx.x & 31;
    const int warp = threadIdx.x >> 5;
    const int gw   = blockIdx.x * WARPS + warp;

    // thread owns dims [lane*8, lane*8+8)
    float4 v0 = *reinterpret_cast<const float4*>(g_v + lane * 8);
    float4 v1 = *reinterpret_cast<const float4*>(g_v + lane * 8 + 4);

    float mx = -CUDART_INF_F;
    float sm = 0.f;
    float acc[8];
#pragma unroll
    for (int i = 0; i < 8; i++) acc[i] = 0.f;

    const float4* base = reinterpret_cast<const float4*>(memory);

    int s0 = gw;
    // two slots per iteration (independent load+dot chains)
    while (s0 + NW < NSLOTS) {
        const float4* r1 = base + (size_t)s0 * (D / 4) + lane * 2;
        const float4* r2 = base + (size_t)(s0 + NW) * (D / 4) + lane * 2;
        float4 a1 = r1[0], b1 = r1[1];
        float4 a2 = r2[0], b2 = r2[1];

        float d1 = a1.x * v0.x; float d2 = a2.x * v0.x;
        d1 = fmaf(a1.y, v0.y, d1); d2 = fmaf(a2.y, v0.y, d2);
        d1 = fmaf(a1.z, v0.z, d1); d2 = fmaf(a2.z, v0.z, d2);
        d1 = fmaf(a1.w, v0.w, d1); d2 = fmaf(a2.w, v0.w, d2);
        d1 = fmaf(b1.x, v1.x, d1); d2 = fmaf(b2.x, v1.x, d2);
        d1 = fmaf(b1.y, v1.y, d1); d2 = fmaf(b2.y, v1.y, d2);
        d1 = fmaf(b1.z, v1.z, d1); d2 = fmaf(b2.z, v1.z, d2);
        d1 = fmaf(b1.w, v1.w, d1); d2 = fmaf(b2.w, v1.w, d2);
#pragma unroll
        for (int m = 16; m >= 1; m >>= 1) {
            d1 += __shfl_xor_sync(0xffffffffu, d1, m);
            d2 += __shfl_xor_sync(0xffffffffu, d2, m);
        }
        float dmax = fmaxf(d1, d2);                 // warp-uniform
        if (dmax > mx) {
            float scale = __expf(mx - dmax);        // 0 on first iter
            mx = dmax;
            sm *= scale;
#pragma unroll
            for (int i = 0; i < 8; i++) acc[i] *= scale;
        }
        float w1 = __expf(d1 - mx);
        float w2 = __expf(d2 - mx);
        sm += w1 + w2;
        acc[0] = fmaf(w1, a1.x, fmaf(w2, a2.x, acc[0]));
        acc[1] = fmaf(w1, a1.y, fmaf(w2, a2.y, acc[1]));
        acc[2] = fmaf(w1, a1.z, fmaf(w2, a2.z, acc[2]));
        acc[3] = fmaf(w1, a1.w, fmaf(w2, a2.w, acc[3]));
        acc[4] = fmaf(w1, b1.x, fmaf(w2, b2.x, acc[4]));
        acc[5] = fmaf(w1, b1.y, fmaf(w2, b2.y, acc[5]));
        acc[6] = fmaf(w1, b1.z, fmaf(w2, b2.z, acc[6]));
        acc[7] = fmaf(w1, b1.w, fmaf(w2, b2.w, acc[7]));
        s0 += 2 * NW;
    }
    if (s0 < NSLOTS) {
        const float4* r1 = base + (size_t)s0 * (D / 4) + lane * 2;
        float4 a1 = r1[0], b1 = r1[1];
        float d = a1.x * v0.x;
        d = fmaf(a1.y, v0.y, d); d = fmaf(a1.z, v0.z, d); d = fmaf(a1.w, v0.w, d);
        d = fmaf(b1.x, v1.x, d); d = fmaf(b1.y, v1.y, d);
        d = fmaf(b1.z, v1.z, d); d = fmaf(b1.w, v1.w, d);
        d = warp_sum(d);
        if (d > mx) {
            float scale = __expf(mx - d);
            mx = d;
            sm *= scale;
#pragma unroll
            for (int i = 0; i < 8; i++) acc[i] *= scale;
        }
        float w = __expf(d - mx);
        sm += w;
        acc[0] = fmaf(w, a1.x, acc[0]); acc[1] = fmaf(w, a1.y, acc[1]);
        acc[2] = fmaf(w, a1.z, acc[2]); acc[3] = fmaf(w, a1.w, acc[3]);
        acc[4] = fmaf(w, b1.x, acc[4]); acc[5] = fmaf(w, b1.y, acc[5]);
        acc[6] = fmaf(w, b1.z, acc[6]); acc[7] = fmaf(w, b1.w, acc[7]);
    }

    // combine the 8 warps of this CTA
    __shared__ float s_mx[WARPS];
    __shared__ float s_sm[WARPS];
    __shared__ float s_acc[WARPS][D];
    if (lane == 0) { s_mx[warp] = mx; s_sm[warp] = sm; }
#pragma unroll
    for (int i = 0; i < 8; i++) s_acc[warp][lane * 8 + i] = acc[i];
    __syncthreads();

    const int t = threadIdx.x;
    float M = s_mx[0];
#pragma unroll
    for (int w = 1; w < WARPS; w++) M = fmaxf(M, s_mx[w]);
    float tot = 0.f;
#pragma unroll
    for (int w = 0; w < WARPS; w++) tot = fmaf(s_acc[w][t], __expf(s_mx[w] - M), tot);
    g_pacc[blockIdx.x * D + t] = tot;
    if (t == 0) {
        float S = 0.f;
#pragma unroll
        for (int w = 0; w < WARPS; w++) S = fmaf(s_sm[w], __expf(s_mx[w] - M), S);
        g_psum[blockIdx.x] = S;
        g_pmax[blockIdx.x] = M;
    }
}

// Reduce CTA partials -> m = memory^T p ; o = C @ m ; u += o ; v = A^T u
__global__ void __launch_bounds__(RTHREADS, 1)
reduce_kernel(const float* __restrict__ A,
              const float* __restrict__ C,
              float* __restrict__ out, int last) {
    __shared__ float sh[RTHREADS];
    __shared__ float m_sh[D];
    __shared__ float u_sh[D];
    __shared__ float gv[4][D];
    const int t = threadIdx.x;
    const int warp = t >> 5, lane = t & 31;
    const int grp = t >> 8, dd = t & 255;

    // global max
    float m = -CUDART_INF_F;
    for (int c = t; c < NBLK; c += RTHREADS) m = fmaxf(m, g_pmax[c]);
    sh[t] = m;
    __syncthreads();
#pragma unroll
    for (int s = RTHREADS / 2; s >= 1; s >>= 1) {
        if (t < s) sh[t] = fmaxf(sh[t], sh[t + s]);
        __syncthreads();
    }
    const float M = sh[0];
    __syncthreads();

    // global sum
    float ssum = 0.f;
    for (int c = t; c < NBLK; c += RTHREADS) ssum = fmaf(g_psum[c], __expf(g_pmax[c] - M), ssum);
    sh[t] = ssum;
    __syncthreads();
#pragma unroll
    for (int s = RTHREADS / 2; s >= 1; s >>= 1) {
        if (t < s) sh[t] += sh[t + s];
        __syncthreads();
    }
    const float S = sh[0];
    __syncthreads();

    // acc: 4 c-groups x 256 dims, coalesced over dd
    float acc = 0.f;
    for (int c = grp; c < NBLK; c += 4)
        acc = fmaf(g_pacc[c * D + dd], __expf(g_pmax[c] - M), acc);
    gv[grp][dd] = acc;
    __syncthreads();
    if (t < D) m_sh[t] = (gv[0][t] + gv[1][t] + gv[2][t] + gv[3][t]) / S;
    __syncthreads();

    // o[row] = C[row,:] . m  — warp per row, coalesced
    for (int row = warp; row < D; row += RTHREADS / 32) {
        const float4* r = reinterpret_cast<const float4*>(C + row * D);
        float4 c0 = r[lane * 2], c1 = r[lane * 2 + 1];
        float d = c0.x * m_sh[lane * 8 + 0] + c0.y * m_sh[lane * 8 + 1]
                + c0.z * m_sh[lane * 8 + 2] + c0.w * m_sh[lane * 8 + 3]
                + c1.x * m_sh[lane * 8 + 4] + c1.y * m_sh[lane * 8 + 5]
                + c1.z * m_sh[lane * 8 + 6] + c1.w * m_sh[lane * 8 + 7];
        d = warp_sum(d);
        if (lane == 0) {
            float u = g_u[row] + d;
            g_u[row] = u;
            u_sh[row] = u;
            if (last) out[row] = u;
        }
    }
    __syncthreads();

    // v[t] = sum_j A[j,t] * u[j] — coalesced over dd, 4 j-groups
    float v = 0.f;
#pragma unroll 8
    for (int j = grp * 64; j < grp * 64 + 64; j++)
        v = fmaf(A[j * D + dd], u_sh[j], v);
    gv[grp][dd] = v;
    __syncthreads();
    if (t < D) g_v[t] = gv[0][t] + gv[1][t] + gv[2][t] + gv[3][t];
}

extern "C" void kernel_launch(void* const* d_in, const int* in_sizes, int n_in,
                              void* d_out, int out_size) {
    const float* memory = (const float*)d_in[0];
    const float* query  = (const float*)d_in[1];
    const float* A      = (const float*)d_in[2];
    const float* B      = (const float*)d_in[3];
    const float* C      = (const float*)d_in[4];
    float* out = (float*)d_out;

    init_kernel<<<1, RTHREADS>>>(query, A, B);
    for (int h = 0; h < 3; h++) {
        flash_kernel<<<NBLK, THREADS>>>(memory);
        reduce_kernel<<<1, RTHREADS>>>(A, C, out, h == 2);
    }
}

// round 3
// speedup vs baseline: 3.2604x; 1.1417x over previous
#include <cuda_runtime.h>
#include <math_constants.h>

#define D      256
#define GRIDN  296
#define BLK    512
#define WPB    16
#define NWARP  (GRIDN * WPB)     // 4736 warps
#define NSLOTS 100000

// ---- device scratch (no allocations allowed) ----
__device__ __align__(16) float g_u0[D];
__device__ __align__(16) float g_v[D];
__device__ __align__(16) float g_m[D];
__device__ __align__(16) float g_msum[D];
__device__ __align__(16) float g_G[D * D];
__device__ float g_pmax[GRIDN];
__device__ float g_psum[GRIDN];
__device__ __align__(16) float g_pacc[GRIDN * D];
__device__ unsigned g_cnt;   // zero-init; always returns to 0
__device__ unsigned g_gen;   // monotonically increasing across replays (ok)

__device__ __forceinline__ void grid_barrier() {
    __syncthreads();
    if (threadIdx.x == 0) {
        unsigned gen = *((volatile unsigned*)&g_gen);
        __threadfence();                       // publish my writes
        if (atomicAdd(&g_cnt, 1u) == GRIDN - 1) {
            g_cnt = 0;
            __threadfence();
            atomicAdd(&g_gen, 1u);             // release
        } else {
            while (*((volatile unsigned*)&g_gen) == gen) { }
        }
        __threadfence();                       // acquire
    }
    __syncthreads();
}

__device__ __forceinline__ float warp_sum(float d) {
#pragma unroll
    for (int m = 16; m >= 1; m >>= 1) d += __shfl_xor_sync(0xffffffffu, d, m);
    return d;
}

__device__ __forceinline__ float block_max(float v, float* sh) {
    const int t = threadIdx.x;
    sh[t] = v; __syncthreads();
#pragma unroll
    for (int s = BLK / 2; s >= 1; s >>= 1) {
        if (t < s) sh[t] = fmaxf(sh[t], sh[t + s]);
        __syncthreads();
    }
    float r = sh[0]; __syncthreads(); return r;
}

__device__ __forceinline__ float block_sum(float v, float* sh) {
    const int t = threadIdx.x;
    sh[t] = v; __syncthreads();
#pragma unroll
    for (int s = BLK / 2; s >= 1; s >>= 1) {
        if (t < s) sh[t] += sh[t + s];
        __syncthreads();
    }
    float r = sh[0]; __syncthreads(); return r;
}

__global__ void __launch_bounds__(BLK, 2)
fused_kernel(const float* __restrict__ memory,
             const float* __restrict__ query,
             const float* __restrict__ A,
             const float* __restrict__ B,
             const float* __restrict__ C,
             float* __restrict__ out) {
    __shared__ float s_mx[WPB], s_sm[WPB];
    __shared__ __align__(16) float s_acc[WPB][D];
    __shared__ float sh[BLK];
    __shared__ float u0s[D];

    const int t    = threadIdx.x;
    const int lane = t & 31;
    const int warp = t >> 5;
    const int bid  = blockIdx.x;

    // ================= phase 0: G = A^T C (CTAs 0..255), u0/v (CTA 256) ===
    if (bid < 256) {
        const int k0 = (bid >> 4) << 4;
        const int t0 = (bid & 15) << 4;
        if (t < 256) {
            const int ii = t >> 4, jj = t & 15;
            float acc = 0.f;
#pragma unroll 4
            for (int dd = 0; dd < D; dd++)
                acc = fmaf(A[dd * D + k0 + ii], C[dd * D + t0 + jj], acc);
            g_G[(k0 + ii) * D + (t0 + jj)] = acc;   // G[k][t] = sum_d A[d][k] C[d][t]
        }
    } else if (bid == 256) {
        if (t < D) sh[t] = query[t];
        __syncthreads();
        // u0[row] = B[row,:] . q  — warp per row
        for (int row = warp; row < D; row += WPB) {
            const float4* r = reinterpret_cast<const float4*>(B + row * D);
            float4 c0 = r[lane * 2], c1 = r[lane * 2 + 1];
            float d = c0.x * sh[lane * 8 + 0] + c0.y * sh[lane * 8 + 1]
                    + c0.z * sh[lane * 8 + 2] + c0.w * sh[lane * 8 + 3]
                    + c1.x * sh[lane * 8 + 4] + c1.y * sh[lane * 8 + 5]
                    + c1.z * sh[lane * 8 + 6] + c1.w * sh[lane * 8 + 7];
            d = warp_sum(d);
            if (lane == 0) { u0s[row] = d; g_u0[row] = d; }
        }
        __syncthreads();
        // v[t] = sum_j A[j][t] u0[j]  (coalesced over t)
        if (t < D) {
            float v = 0.f;
#pragma unroll 8
            for (int j = 0; j < D; j++) v = fmaf(A[j * D + t], u0s[j], v);
            g_v[t] = v;
        }
    }
    grid_barrier();

    float msum_reg = 0.f;   // per-CTA-j running sum of m_j (same in all threads)

    for (int hop = 0; hop < 3; hop++) {
        // ================= flash pass: online softmax over all slots =======
        {
            float4 v0 = __ldcg(reinterpret_cast<const float4*>(g_v + lane * 8));
            float4 v1 = __ldcg(reinterpret_cast<const float4*>(g_v + lane * 8 + 4));

            float mx = -CUDART_INF_F, sm = 0.f;
            float acc[8];
#pragma unroll
            for (int i = 0; i < 8; i++) acc[i] = 0.f;

            const float4* base = reinterpret_cast<const float4*>(memory);
            const int gw = bid * WPB + warp;
            int s0 = gw;

            while (s0 + NWARP < NSLOTS) {
                const float4* r1 = base + (size_t)s0 * (D / 4) + lane * 2;
                const float4* r2 = base + (size_t)(s0 + NWARP) * (D / 4) + lane * 2;
                // L2 prefetch one iteration ahead
                int sp = s0 + 2 * NWARP;
                if (sp + NWARP < NSLOTS) {
                    const void* p1 = (const void*)(base + (size_t)sp * (D / 4) + lane * 2);
                    const void* p2 = (const void*)(base + (size_t)(sp + NWARP) * (D / 4) + lane * 2);
                    asm volatile("prefetch.global.L2 [%0];" :: "l"(p1));
                    asm volatile("prefetch.global.L2 [%0];" :: "l"(p2));
                }
                float4 a1 = r1[0], b1 = r1[1];
                float4 a2 = r2[0], b2 = r2[1];

                float d1 = a1.x * v0.x;           float d2 = a2.x * v0.x;
                d1 = fmaf(a1.y, v0.y, d1);        d2 = fmaf(a2.y, v0.y, d2);
                d1 = fmaf(a1.z, v0.z, d1);        d2 = fmaf(a2.z, v0.z, d2);
                d1 = fmaf(a1.w, v0.w, d1);        d2 = fmaf(a2.w, v0.w, d2);
                d1 = fmaf(b1.x, v1.x, d1);        d2 = fmaf(b2.x, v1.x, d2);
                d1 = fmaf(b1.y, v1.y, d1);        d2 = fmaf(b2.y, v1.y, d2);
                d1 = fmaf(b1.z, v1.z, d1);        d2 = fmaf(b2.z, v1.z, d2);
                d1 = fmaf(b1.w, v1.w, d1);        d2 = fmaf(b2.w, v1.w, d2);
#pragma unroll
                for (int m = 16; m >= 1; m >>= 1) {
                    d1 += __shfl_xor_sync(0xffffffffu, d1, m);
                    d2 += __shfl_xor_sync(0xffffffffu, d2, m);
                }
                float dmax = fmaxf(d1, d2);        // warp-uniform
                if (dmax > mx) {
                    float scale = __expf(mx - dmax);   // 0 on first iter
                    mx = dmax;
                    sm *= scale;
#pragma unroll
                    for (int i = 0; i < 8; i++) acc[i] *= scale;
                }
                float w1 = __expf(d1 - mx);
                float w2 = __expf(d2 - mx);
                sm += w1 + w2;
                acc[0] = fmaf(w1, a1.x, fmaf(w2, a2.x, acc[0]));
                acc[1] = fmaf(w1, a1.y, fmaf(w2, a2.y, acc[1]));
                acc[2] = fmaf(w1, a1.z, fmaf(w2, a2.z, acc[2]));
                acc[3] = fmaf(w1, a1.w, fmaf(w2, a2.w, acc[3]));
                acc[4] = fmaf(w1, b1.x, fmaf(w2, b2.x, acc[4]));
                acc[5] = fmaf(w1, b1.y, fmaf(w2, b2.y, acc[5]));
                acc[6] = fmaf(w1, b1.z, fmaf(w2, b2.z, acc[6]));
                acc[7] = fmaf(w1, b1.w, fmaf(w2, b2.w, acc[7]));
                s0 += 2 * NWARP;
            }
            while (s0 < NSLOTS) {
                const float4* r1 = base + (size_t)s0 * (D / 4) + lane * 2;
                float4 a1 = r1[0], b1 = r1[1];
                float d = a1.x * v0.x;
                d = fmaf(a1.y, v0.y, d); d = fmaf(a1.z, v0.z, d); d = fmaf(a1.w, v0.w, d);
                d = fmaf(b1.x, v1.x, d); d = fmaf(b1.y, v1.y, d);
                d = fmaf(b1.z, v1.z, d); d = fmaf(b1.w, v1.w, d);
                d = warp_sum(d);
                if (d > mx) {
                    float scale = __expf(mx - d);
                    mx = d; sm *= scale;
#pragma unroll
                    for (int i = 0; i < 8; i++) acc[i] *= scale;
                }
                float w = __expf(d - mx);
                sm += w;
                acc[0] = fmaf(w, a1.x, acc[0]); acc[1] = fmaf(w, a1.y, acc[1]);
                acc[2] = fmaf(w, a1.z, acc[2]); acc[3] = fmaf(w, a1.w, acc[3]);
                acc[4] = fmaf(w, b1.x, acc[4]); acc[5] = fmaf(w, b1.y, acc[5]);
                acc[6] = fmaf(w, b1.z, acc[6]); acc[7] = fmaf(w, b1.w, acc[7]);
                s0 += NWARP;
            }

            // CTA combine
            if (lane == 0) { s_mx[warp] = mx; s_sm[warp] = sm; }
#pragma unroll
            for (int i = 0; i < 8; i++) s_acc[warp][lane * 8 + i] = acc[i];
            __syncthreads();
            if (t < D) {
                float M = s_mx[0];
#pragma unroll
                for (int w = 1; w < WPB; w++) M = fmaxf(M, s_mx[w]);
                float tot = 0.f;
#pragma unroll
                for (int w = 0; w < WPB; w++) tot = fmaf(s_acc[w][t], __expf(s_mx[w] - M), tot);
                g_pacc[bid * D + t] = tot;
                if (t == 0) {
                    float S = 0.f;
#pragma unroll
                    for (int w = 0; w < WPB; w++) S = fmaf(s_sm[w], __expf(s_mx[w] - M), S);
                    g_psum[bid] = S;
                    g_pmax[bid] = M;
                }
            }
            __syncthreads();
        }
        grid_barrier();

        // ================= stage 1: CTA j computes m[j] =====================
        if (bid < 256) {
            float pm = (t < GRIDN) ? __ldcg(&g_pmax[t]) : -CUDART_INF_F;
            float M  = block_max(pm, sh);
            float ws = (t < GRIDN) ? __expf(pm - M) : 0.f;
            float S  = block_sum((t < GRIDN) ? ws * __ldcg(&g_psum[t]) : 0.f, sh);
            float pa = (t < GRIDN) ? ws * __ldcg(&g_pacc[t * D + bid]) : 0.f;
            float mj = block_sum(pa, sh) / S;
            msum_reg += mj;
            if (t == 0) {
                g_m[bid]    = mj;
                g_msum[bid] = msum_reg;
            }
        }
        grid_barrier();

        // ================= stage 2: v += G m   (or final output) ===========
        if (hop < 2) {
            if (bid < 256) {
                float p = (t < D) ? __ldcg(&g_G[bid * D + t]) * __ldcg(&g_m[t]) : 0.f;
                float dv = block_sum(p, sh);
                if (t == 0) g_v[bid] = __ldcg(&g_v[bid]) + dv;
            }
            grid_barrier();
        } else {
            if (bid < 256) {
                float p = (t < D) ? C[bid * D + t] * __ldcg(&g_msum[t]) : 0.f;
                float o = block_sum(p, sh);
                if (t == 0) out[bid] = __ldcg(&g_u0[bid]) + o;
            }
        }
    }
}

extern "C" void kernel_launch(void* const* d_in, const int* in_sizes, int n_in,
                              void* d_out, int out_size) {
    const float* memory = (const float*)d_in[0];
    const float* query  = (const float*)d_in[1];
    const float* A      = (const float*)d_in[2];
    const float* B      = (const float*)d_in[3];
    const float* C      = (const float*)d_in[4];
    float* out = (float*)d_out;

    fused_kernel<<<GRIDN, BLK>>>(memory, query, A, B, C, out);
}

// round 4
// speedup vs baseline: 4.4274x; 1.3579x over previous
#include <cuda_runtime.h>
#include <math_constants.h>

#define D        256
#define NBLK     592          // flash grid: 4 CTAs per SM
#define THREADS  256
#define WARPS    (THREADS / 32)
#define NW       (NBLK * WARPS)     // 4736 warps
#define NSLOTS   100000
#define RBLK     512

// ---- device scratch (no allocations allowed) ----
__device__ __align__(16) float g_u0[D];
__device__ __align__(16) float g_v[D];
__device__ __align__(16) float g_m[D];
__device__ __align__(16) float g_msum[D];
__device__ __align__(16) float g_G[D * D];
__device__ float g_pmax[NBLK];
__device__ float g_psum[NBLK];
__device__ __align__(16) float g_pacc[D * NBLK];   // TRANSPOSED: [dim][cta]

__device__ __forceinline__ float warp_sum(float d) {
#pragma unroll
    for (int m = 16; m >= 1; m >>= 1) d += __shfl_xor_sync(0xffffffffu, d, m);
    return d;
}

// ---------------- G = A^T C : CTA k computes row k of G -------------------
__global__ void __launch_bounds__(256, 4)
gmat_kernel(const float* __restrict__ A, const float* __restrict__ C) {
    __shared__ float colA[D];
    const int k = blockIdx.x, t = threadIdx.x;
    colA[t] = A[t * D + k];          // column k of A (one strided round)
    __syncthreads();
    float acc = 0.f;
#pragma unroll 8
    for (int dd = 0; dd < D; dd++)
        acc = fmaf(colA[dd], C[dd * D + t], acc);
    g_G[k * D + t] = acc;
}

// ---------------- u0 = B q ; v0 = A^T u0 ----------------------------------
__global__ void __launch_bounds__(1024, 1)
init_kernel(const float* __restrict__ q,
            const float* __restrict__ A,
            const float* __restrict__ B) {
    __shared__ float qs[D];
    __shared__ float us[D];
    __shared__ float gv[4][D];
    const int t = threadIdx.x, warp = t >> 5, lane = t & 31;
    if (t < D) qs[t] = q[t];
    __syncthreads();
    for (int row = warp; row < D; row += 32) {
        const float4* r = reinterpret_cast<const float4*>(B + row * D);
        float4 c0 = r[lane * 2], c1 = r[lane * 2 + 1];
        float d = c0.x * qs[lane * 8 + 0] + c0.y * qs[lane * 8 + 1]
                + c0.z * qs[lane * 8 + 2] + c0.w * qs[lane * 8 + 3]
                + c1.x * qs[lane * 8 + 4] + c1.y * qs[lane * 8 + 5]
                + c1.z * qs[lane * 8 + 6] + c1.w * qs[lane * 8 + 7];
        d = warp_sum(d);
        if (lane == 0) { us[row] = d; g_u0[row] = d; }
    }
    __syncthreads();
    const int grp = t >> 8, dd = t & 255;
    float v = 0.f;
#pragma unroll 8
    for (int j = grp * 64; j < grp * 64 + 64; j++)
        v = fmaf(A[j * D + dd], us[j], v);
    gv[grp][dd] = v;
    __syncthreads();
    if (t < D) g_v[t] = gv[0][t] + gv[1][t] + gv[2][t] + gv[3][t];
}

// ---------------- flash pass (identical hot loop to R2) --------------------
__global__ void __launch_bounds__(THREADS, 4)
flash_kernel(const float* __restrict__ memory) {
    const int lane = threadIdx.x & 31;
    const int warp = threadIdx.x >> 5;
    const int gw   = blockIdx.x * WARPS + warp;

    float4 v0 = *reinterpret_cast<const float4*>(g_v + lane * 8);
    float4 v1 = *reinterpret_cast<const float4*>(g_v + lane * 8 + 4);

    float mx = -CUDART_INF_F, sm = 0.f;
    float acc[8];
#pragma unroll
    for (int i = 0; i < 8; i++) acc[i] = 0.f;

    const float4* base = reinterpret_cast<const float4*>(memory);
    int s0 = gw;
    while (s0 + NW < NSLOTS) {
        const float4* r1 = base + (size_t)s0 * (D / 4) + lane * 2;
        const float4* r2 = base + (size_t)(s0 + NW) * (D / 4) + lane * 2;
        float4 a1 = r1[0], b1 = r1[1];
        float4 a2 = r2[0], b2 = r2[1];

        float d1 = a1.x * v0.x;     float d2 = a2.x * v0.x;
        d1 = fmaf(a1.y, v0.y, d1);  d2 = fmaf(a2.y, v0.y, d2);
        d1 = fmaf(a1.z, v0.z, d1);  d2 = fmaf(a2.z, v0.z, d2);
        d1 = fmaf(a1.w, v0.w, d1);  d2 = fmaf(a2.w, v0.w, d2);
        d1 = fmaf(b1.x, v1.x, d1);  d2 = fmaf(b2.x, v1.x, d2);
        d1 = fmaf(b1.y, v1.y, d1);  d2 = fmaf(b2.y, v1.y, d2);
        d1 = fmaf(b1.z, v1.z, d1);  d2 = fmaf(b2.z, v1.z, d2);
        d1 = fmaf(b1.w, v1.w, d1);  d2 = fmaf(b2.w, v1.w, d2);
#pragma unroll
        for (int m = 16; m >= 1; m >>= 1) {
            d1 += __shfl_xor_sync(0xffffffffu, d1, m);
            d2 += __shfl_xor_sync(0xffffffffu, d2, m);
        }
        float dmax = fmaxf(d1, d2);
        if (dmax > mx) {                       // warp-uniform
            float scale = __expf(mx - dmax);
            mx = dmax; sm *= scale;
#pragma unroll
            for (int i = 0; i < 8; i++) acc[i] *= scale;
        }
        float w1 = __expf(d1 - mx);
        float w2 = __expf(d2 - mx);
        sm += w1 + w2;
        acc[0] = fmaf(w1, a1.x, fmaf(w2, a2.x, acc[0]));
        acc[1] = fmaf(w1, a1.y, fmaf(w2, a2.y, acc[1]));
        acc[2] = fmaf(w1, a1.z, fmaf(w2, a2.z, acc[2]));
        acc[3] = fmaf(w1, a1.w, fmaf(w2, a2.w, acc[3]));
        acc[4] = fmaf(w1, b1.x, fmaf(w2, b2.x, acc[4]));
        acc[5] = fmaf(w1, b1.y, fmaf(w2, b2.y, acc[5]));
        acc[6] = fmaf(w1, b1.z, fmaf(w2, b2.z, acc[6]));
        acc[7] = fmaf(w1, b1.w, fmaf(w2, b2.w, acc[7]));
        s0 += 2 * NW;
    }
    if (s0 < NSLOTS) {
        const float4* r1 = base + (size_t)s0 * (D / 4) + lane * 2;
        float4 a1 = r1[0], b1 = r1[1];
        float d = a1.x * v0.x;
        d = fmaf(a1.y, v0.y, d); d = fmaf(a1.z, v0.z, d); d = fmaf(a1.w, v0.w, d);
        d = fmaf(b1.x, v1.x, d); d = fmaf(b1.y, v1.y, d);
        d = fmaf(b1.z, v1.z, d); d = fmaf(b1.w, v1.w, d);
        d = warp_sum(d);
        if (d > mx) {
            float scale = __expf(mx - d);
            mx = d; sm *= scale;
#pragma unroll
            for (int i = 0; i < 8; i++) acc[i] *= scale;
        }
        float w = __expf(d - mx);
        sm += w;
        acc[0] = fmaf(w, a1.x, acc[0]); acc[1] = fmaf(w, a1.y, acc[1]);
        acc[2] = fmaf(w, a1.z, acc[2]); acc[3] = fmaf(w, a1.w, acc[3]);
        acc[4] = fmaf(w, b1.x, acc[4]); acc[5] = fmaf(w, b1.y, acc[5]);
        acc[6] = fmaf(w, b1.z, acc[6]); acc[7] = fmaf(w, b1.w, acc[7]);
    }

    __shared__ float s_mx[WARPS], s_sm[WARPS];
    __shared__ float s_acc[WARPS][D];
    if (lane == 0) { s_mx[warp] = mx; s_sm[warp] = sm; }
#pragma unroll
    for (int i = 0; i < 8; i++) s_acc[warp][lane * 8 + i] = acc[i];
    __syncthreads();

    const int t = threadIdx.x;
    float M = s_mx[0];
#pragma unroll
    for (int w = 1; w < WARPS; w++) M = fmaxf(M, s_mx[w]);
    float tot = 0.f;
#pragma unroll
    for (int w = 0; w < WARPS; w++) tot = fmaf(s_acc[w][t], __expf(s_mx[w] - M), tot);
    g_pacc[t * NBLK + blockIdx.x] = tot;       // transposed for reduce
    if (t == 0) {
        float S = 0.f;
#pragma unroll
        for (int w = 0; w < WARPS; w++) S = fmaf(s_sm[w], __expf(s_mx[w] - M), S);
        g_psum[blockIdx.x] = S;
        g_pmax[blockIdx.x] = M;
    }
}

// ---------------- distributed reduce: CTA j -> m[j] -----------------------
__global__ void __launch_bounds__(RBLK, 2)
reduce_kernel(int hop) {
    __shared__ float sh[RBLK];
    const int j = blockIdx.x, t = threadIdx.x;

    float pm0 = (t < NBLK) ? g_pmax[t] : -CUDART_INF_F;
    float pm1 = (t + RBLK < NBLK) ? g_pmax[t + RBLK] : -CUDART_INF_F;
    float m = fmaxf(pm0, pm1);
    sh[t] = m; __syncthreads();
#pragma unroll
    for (int s = RBLK / 2; s >= 1; s >>= 1) {
        if (t < s) sh[t] = fmaxf(sh[t], sh[t + s]);
        __syncthreads();
    }
    const float M = sh[0];
    __syncthreads();

    float w0 = (t < NBLK) ? __expf(pm0 - M) : 0.f;
    float w1 = (t + RBLK < NBLK) ? __expf(pm1 - M) : 0.f;

    float ssum = 0.f;
    if (t < NBLK)        ssum = fmaf(w0, g_psum[t], ssum);
    if (t + RBLK < NBLK) ssum = fmaf(w1, g_psum[t + RBLK], ssum);
    sh[t] = ssum; __syncthreads();
#pragma unroll
    for (int s = RBLK / 2; s >= 1; s >>= 1) {
        if (t < s) sh[t] += sh[t + s];
        __syncthreads();
    }
    const float S = sh[0];
    __syncthreads();

    float pa = 0.f;
    if (t < NBLK)        pa = fmaf(w0, g_pacc[j * NBLK + t], pa);
    if (t + RBLK < NBLK) pa = fmaf(w1, g_pacc[j * NBLK + t + RBLK], pa);
    sh[t] = pa; __syncthreads();
#pragma unroll
    for (int s = RBLK / 2; s >= 1; s >>= 1) {
        if (t < s) sh[t] += sh[t + s];
        __syncthreads();
    }
    if (t == 0) {
        float mj = sh[0] / S;
        g_m[j] = mj;
        g_msum[j] = (hop == 0) ? mj : g_msum[j] + mj;
    }
}

// ---------------- v += G m   (warp per row) --------------------------------
__global__ void __launch_bounds__(RBLK, 2)
vupd_kernel() {
    const int t = threadIdx.x, warp = t >> 5, lane = t & 31;
    const int row = blockIdx.x * (RBLK / 32) + warp;
    const float4* r = reinterpret_cast<const float4*>(g_G + row * D) + lane * 2;
    const float4* mm = reinterpret_cast<const float4*>(g_m) + lane * 2;
    float4 c0 = r[0], c1 = r[1];
    float4 m0 = mm[0], m1 = mm[1];
    float d = c0.x * m0.x + c0.y * m0.y + c0.z * m0.z + c0.w * m0.w
            + c1.x * m1.x + c1.y * m1.y + c1.z * m1.z + c1.w * m1.w;
    d = warp_sum(d);
    if (lane == 0) g_v[row] += d;
}

// ---------------- out = u0 + C msum  (warp per row) ------------------------
__global__ void __launch_bounds__(RBLK, 2)
final_kernel(const float* __restrict__ C, float* __restrict__ out) {
    const int t = threadIdx.x, warp = t >> 5, lane = t & 31;
    const int row = blockIdx.x * (RBLK / 32) + warp;
    const float4* r = reinterpret_cast<const float4*>(C + row * D) + lane * 2;
    const float4* mm = reinterpret_cast<const float4*>(g_msum) + lane * 2;
    float4 c0 = r[0], c1 = r[1];
    float4 m0 = mm[0], m1 = mm[1];
    float d = c0.x * m0.x + c0.y * m0.y + c0.z * m0.z + c0.w * m0.w
            + c1.x * m1.x + c1.y * m1.y + c1.z * m1.z + c1.w * m1.w;
    d = warp_sum(d);
    if (lane == 0) out[row] = g_u0[row] + d;
}

extern "C" void kernel_launch(void* const* d_in, const int* in_sizes, int n_in,
                              void* d_out, int out_size) {
    const float* memory = (const float*)d_in[0];
    const float* query  = (const float*)d_in[1];
    const float* A      = (const float*)d_in[2];
    const float* B      = (const float*)d_in[3];
    const float* C      = (const float*)d_in[4];
    float* out = (float*)d_out;

    gmat_kernel<<<256, 256>>>(A, C);
    init_kernel<<<1, 1024>>>(query, A, B);
    for (int h = 0; h < 3; h++) {
        flash_kernel<<<NBLK, THREADS>>>(memory);
        reduce_kernel<<<256, RBLK>>>(h);
        if (h < 2) vupd_kernel<<<16, RBLK>>>();
        else       final_kernel<<<16, RBLK>>>(C, out);
    }
}

// round 6
// speedup vs baseline: 4.7841x; 1.0806x over previous
#include <cuda_runtime.h>
#include <math_constants.h>

#define D        256
#define NBLK     592          // flash grid: 4 CTAs per SM
#define THREADS  256
#define WARPS    (THREADS / 32)
#define NW       (NBLK * WARPS)     // 4736 warps
#define NSLOTS   100000
#define RBLK     512

// ---- device scratch (no allocations allowed) ----
__device__ __align__(16) float g_u0[D];
__device__ __align__(16) float g_v[D];
__device__ __align__(16) float g_m[D];
__device__ __align__(16) float g_msum[D];
__device__ __align__(16) float g_G[D * D];
__device__ float g_pmax[NBLK];
__device__ float g_psum[NBLK];
__device__ __align__(16) float g_pacc[D * NBLK];   // TRANSPOSED: [dim][cta]

__device__ __forceinline__ float warp_sum(float d) {
#pragma unroll
    for (int m = 16; m >= 1; m >>= 1) d += __shfl_xor_sync(0xffffffffu, d, m);
    return d;
}
__device__ __forceinline__ float warp_max(float d) {
#pragma unroll
    for (int m = 16; m >= 1; m >>= 1) d = fmaxf(d, __shfl_xor_sync(0xffffffffu, d, m));
    return d;
}

// 32B L2-persistent load: one v8.b32 per slot-half (sm_103 requires v8 width
// with .L2::evict_last). Keeps `memory` L2-resident across passes/replays.
__device__ __forceinline__ void ldg_el8(const void* p, float4& a, float4& b) {
    unsigned r0, r1, r2, r3, r4, r5, r6, r7;
    asm("ld.global.nc.L2::evict_last.v8.b32 {%0,%1,%2,%3,%4,%5,%6,%7}, [%8];"
        : "=r"(r0), "=r"(r1), "=r"(r2), "=r"(r3),
          "=r"(r4), "=r"(r5), "=r"(r6), "=r"(r7) : "l"(p));
    a.x = __uint_as_float(r0); a.y = __uint_as_float(r1);
    a.z = __uint_as_float(r2); a.w = __uint_as_float(r3);
    b.x = __uint_as_float(r4); b.y = __uint_as_float(r5);
    b.z = __uint_as_float(r6); b.w = __uint_as_float(r7);
}

// ---- setup: blocks 0..255 compute G = A^T C ; block 256 computes u0, v0 ----
__global__ void __launch_bounds__(256, 4)
setup_kernel(const float* __restrict__ A, const float* __restrict__ B,
             const float* __restrict__ C, const float* __restrict__ q) {
    const int t = threadIdx.x;
    if (blockIdx.x < 256) {
        __shared__ float colA[D];
        const int k = blockIdx.x;
        colA[t] = A[t * D + k];          // column k of A
        __syncthreads();
        float acc = 0.f;
#pragma unroll 8
        for (int dd = 0; dd < D; dd++)
            acc = fmaf(colA[dd], C[dd * D + t], acc);
        g_G[k * D + t] = acc;            // G[k][t] = sum_d A[d][k] C[d][t]
    } else {
        __shared__ float qs[D];
        __shared__ float us[D];
        const int warp = t >> 5, lane = t & 31;
        qs[t] = q[t];
        __syncthreads();
        // u0[row] = B[row,:].q  — warp per row
        for (int row = warp; row < D; row += 8) {
            const float4* r = reinterpret_cast<const float4*>(B + row * D);
            float4 c0 = r[lane * 2], c1 = r[lane * 2 + 1];
            float d = c0.x * qs[lane * 8 + 0] + c0.y * qs[lane * 8 + 1]
                    + c0.z * qs[lane * 8 + 2] + c0.w * qs[lane * 8 + 3]
                    + c1.x * qs[lane * 8 + 4] + c1.y * qs[lane * 8 + 5]
                    + c1.z * qs[lane * 8 + 6] + c1.w * qs[lane * 8 + 7];
            d = warp_sum(d);
            if (lane == 0) { us[row] = d; g_u0[row] = d; }
        }
        __syncthreads();
        // v0[t] = sum_j A[j][t] u0[j]  (coalesced over t)
        float v = 0.f;
#pragma unroll 8
        for (int j = 0; j < D; j++) v = fmaf(A[j * D + t], us[j], v);
        g_v[t] = v;
    }
}

// ---------------- flash pass: fused score+softmax+weighted-sum ------------
__global__ void __launch_bounds__(THREADS, 4)
flash_kernel(const float* __restrict__ memory) {
    const int lane = threadIdx.x & 31;
    const int warp = threadIdx.x >> 5;
    const int gw   = blockIdx.x * WARPS + warp;

    float4 v0 = *reinterpret_cast<const float4*>(g_v + lane * 8);
    float4 v1 = *reinterpret_cast<const float4*>(g_v + lane * 8 + 4);

    float mx = -CUDART_INF_F, sm = 0.f;
    float acc[8];
#pragma unroll
    for (int i = 0; i < 8; i++) acc[i] = 0.f;

    const char* base = reinterpret_cast<const char*>(memory);
    const int loff = lane * 32;          // 32 bytes per lane per slot
    int s0 = gw;
    while (s0 + NW < NSLOTS) {
        const void* r1 = base + (size_t)s0 * 1024 + loff;
        const void* r2 = base + (size_t)(s0 + NW) * 1024 + loff;
        float4 a1, b1, a2, b2;
        ldg_el8(r1, a1, b1);
        ldg_el8(r2, a2, b2);

        float d1 = a1.x * v0.x;     float d2 = a2.x * v0.x;
        d1 = fmaf(a1.y, v0.y, d1);  d2 = fmaf(a2.y, v0.y, d2);
        d1 = fmaf(a1.z, v0.z, d1);  d2 = fmaf(a2.z, v0.z, d2);
        d1 = fmaf(a1.w, v0.w, d1);  d2 = fmaf(a2.w, v0.w, d2);
        d1 = fmaf(b1.x, v1.x, d1);  d2 = fmaf(b2.x, v1.x, d2);
        d1 = fmaf(b1.y, v1.y, d1);  d2 = fmaf(b2.y, v1.y, d2);
        d1 = fmaf(b1.z, v1.z, d1);  d2 = fmaf(b2.z, v1.z, d2);
        d1 = fmaf(b1.w, v1.w, d1);  d2 = fmaf(b2.w, v1.w, d2);
#pragma unroll
        for (int m = 16; m >= 1; m >>= 1) {
            d1 += __shfl_xor_sync(0xffffffffu, d1, m);
            d2 += __shfl_xor_sync(0xffffffffu, d2, m);
        }
        float dmax = fmaxf(d1, d2);
        if (dmax > mx) {                       // warp-uniform branch
            float scale = __expf(mx - dmax);
            mx = dmax; sm *= scale;
#pragma unroll
            for (int i = 0; i < 8; i++) acc[i] *= scale;
        }
        float w1 = __expf(d1 - mx);
        float w2 = __expf(d2 - mx);
        sm += w1 + w2;
        acc[0] = fmaf(w1, a1.x, fmaf(w2, a2.x, acc[0]));
        acc[1] = fmaf(w1, a1.y, fmaf(w2, a2.y, acc[1]));
        acc[2] = fmaf(w1, a1.z, fmaf(w2, a2.z, acc[2]));
        acc[3] = fmaf(w1, a1.w, fmaf(w2, a2.w, acc[3]));
        acc[4] = fmaf(w1, b1.x, fmaf(w2, b2.x, acc[4]));
        acc[5] = fmaf(w1, b1.y, fmaf(w2, b2.y, acc[5]));
        acc[6] = fmaf(w1, b1.z, fmaf(w2, b2.z, acc[6]));
        acc[7] = fmaf(w1, b1.w, fmaf(w2, b2.w, acc[7]));
        s0 += 2 * NW;
    }
    if (s0 < NSLOTS) {
        const void* r1 = base + (size_t)s0 * 1024 + loff;
        float4 a1, b1;
        ldg_el8(r1, a1, b1);
        float d = a1.x * v0.x;
        d = fmaf(a1.y, v0.y, d); d = fmaf(a1.z, v0.z, d); d = fmaf(a1.w, v0.w, d);
        d = fmaf(b1.x, v1.x, d); d = fmaf(b1.y, v1.y, d);
        d = fmaf(b1.z, v1.z, d); d = fmaf(b1.w, v1.w, d);
        d = warp_sum(d);
        if (d > mx) {
            float scale = __expf(mx - d);
            mx = d; sm *= scale;
#pragma unroll
            for (int i = 0; i < 8; i++) acc[i] *= scale;
        }
        float w = __expf(d - mx);
        sm += w;
        acc[0] = fmaf(w, a1.x, acc[0]); acc[1] = fmaf(w, a1.y, acc[1]);
        acc[2] = fmaf(w, a1.z, acc[2]); acc[3] = fmaf(w, a1.w, acc[3]);
        acc[4] = fmaf(w, b1.x, acc[4]); acc[5] = fmaf(w, b1.y, acc[5]);
        acc[6] = fmaf(w, b1.z, acc[6]); acc[7] = fmaf(w, b1.w, acc[7]);
    }

    __shared__ float s_mx[WARPS], s_sm[WARPS];
    __shared__ float s_acc[WARPS][D];
    if (lane == 0) { s_mx[warp] = mx; s_sm[warp] = sm; }
#pragma unroll
    for (int i = 0; i < 8; i++) s_acc[warp][lane * 8 + i] = acc[i];
    __syncthreads();

    const int t = threadIdx.x;
    float M = s_mx[0];
#pragma unroll
    for (int w = 1; w < WARPS; w++) M = fmaxf(M, s_mx[w]);
    float tot = 0.f;
#pragma unroll
    for (int w = 0; w < WARPS; w++) tot = fmaf(s_acc[w][t], __expf(s_mx[w] - M), tot);
    g_pacc[t * NBLK + blockIdx.x] = tot;       // transposed for reduce
    if (t == 0) {
        float S = 0.f;
#pragma unroll
        for (int w = 0; w < WARPS; w++) S = fmaf(s_sm[w], __expf(s_mx[w] - M), S);
        g_psum[blockIdx.x] = S;
        g_pmax[blockIdx.x] = M;
    }
}

// ---------------- distributed reduce: CTA j -> m[j]  (shfl-based) ---------
__global__ void __launch_bounds__(RBLK, 2)
reduce_kernel(int hop) {
    __shared__ float s1[16], s2[16];
    __shared__ float sM;
    const int j = blockIdx.x, t = threadIdx.x;
    const int warp = t >> 5, lane = t & 31;

    // hoist all loads (hide latency above the max chain)
    const bool v0ok = (t < NBLK), v1ok = (t + RBLK < NBLK);
    float pm0 = v0ok ? g_pmax[t] : -CUDART_INF_F;
    float pm1 = v1ok ? g_pmax[t + RBLK] : -CUDART_INF_F;
    float ps0 = v0ok ? g_psum[t] : 0.f;
    float ps1 = v1ok ? g_psum[t + RBLK] : 0.f;
    float pa0 = v0ok ? g_pacc[j * NBLK + t] : 0.f;
    float pa1 = v1ok ? g_pacc[j * NBLK + t + RBLK] : 0.f;

    // global max: warp shfl -> 16 partials -> warp 0
    float mx = warp_max(fmaxf(pm0, pm1));
    if (lane == 0) s1[warp] = mx;
    __syncthreads();
    if (warp == 0) {
        float v = (lane < 16) ? s1[lane] : -CUDART_INF_F;
        v = warp_max(v);
        if (lane == 0) sM = v;
    }
    __syncthreads();
    const float M = sM;

    // combined (sum, acc) reduction
    float w0 = v0ok ? __expf(pm0 - M) : 0.f;
    float w1 = v1ok ? __expf(pm1 - M) : 0.f;
    float ss = fmaf(w0, ps0, w1 * ps1);
    float pa = fmaf(w0, pa0, w1 * pa1);
#pragma unroll
    for (int m = 16; m >= 1; m >>= 1) {
        ss += __shfl_xor_sync(0xffffffffu, ss, m);
        pa += __shfl_xor_sync(0xffffffffu, pa, m);
    }
    if (lane == 0) { s1[warp] = ss; s2[warp] = pa; }
    __syncthreads();
    if (warp == 0) {
        float a = (lane < 16) ? s1[lane] : 0.f;
        float b = (lane < 16) ? s2[lane] : 0.f;
#pragma unroll
        for (int m = 16; m >= 1; m >>= 1) {
            a += __shfl_xor_sync(0xffffffffu, a, m);
            b += __shfl_xor_sync(0xffffffffu, b, m);
        }
        if (lane == 0) {
            float mj = b / a;
            g_m[j] = mj;
            g_msum[j] = (hop == 0) ? mj : g_msum[j] + mj;
        }
    }
}

// ---------------- v += G m   (warp per row) --------------------------------
__global__ void __launch_bounds__(RBLK, 2)
vupd_kernel() {
    const int t = threadIdx.x, warp = t >> 5, lane = t & 31;
    const int row = blockIdx.x * (RBLK / 32) + warp;
    const float4* r  = reinterpret_cast<const float4*>(g_G + row * D) + lane * 2;
    const float4* mm = reinterpret_cast<const float4*>(g_m) + lane * 2;
    float4 c0 = r[0], c1 = r[1];
    float4 m0 = mm[0], m1 = mm[1];
    float d = c0.x * m0.x + c0.y * m0.y + c0.z * m0.z + c0.w * m0.w
            + c1.x * m1.x + c1.y * m1.y + c1.z * m1.z + c1.w * m1.w;
    d = warp_sum(d);
    if (lane == 0) g_v[row] += d;
}

// ---------------- out = u0 + C msum  (warp per row) ------------------------
__global__ void __launch_bounds__(RBLK, 2)
final_kernel(const float* __restrict__ C, float* __restrict__ out) {
    const int t = threadIdx.x, warp = t >> 5, lane = t & 31;
    const int row = blockIdx.x * (RBLK / 32) + warp;
    const float4* r  = reinterpret_cast<const float4*>(C + row * D) + lane * 2;
    const float4* mm = reinterpret_cast<const float4*>(g_msum) + lane * 2;
    float4 c0 = r[0], c1 = r[1];
    float4 m0 = mm[0], m1 = mm[1];
    float d = c0.x * m0.x + c0.y * m0.y + c0.z * m0.z + c0.w * m0.w
            + c1.x * m1.x + c1.y * m1.y + c1.z * m1.z + c1.w * m1.w;
    d = warp_sum(d);
    if (lane == 0) out[row] = g_u0[row] + d;
}

extern "C" void kernel_launch(void* const* d_in, const int* in_sizes, int n_in,
                              void* d_out, int out_size) {
    const float* memory = (const float*)d_in[0];
    const float* query  = (const float*)d_in[1];
    const float* A      = (const float*)d_in[2];
    const float* B      = (const float*)d_in[3];
    const float* C      = (const float*)d_in[4];
    float* out = (float*)d_out;

    setup_kernel<<<257, 256>>>(A, B, C, query);
    for (int h = 0; h < 3; h++) {
        flash_kernel<<<NBLK, THREADS>>>(memory);
        reduce_kernel<<<256, RBLK>>>(h);
        if (h < 2) vupd_kernel<<<16, RBLK>>>();
        else       final_kernel<<<16, RBLK>>>(C, out);
    }
}